// round 2
// baseline (speedup 1.0000x reference)
#include <cuda_runtime.h>
#include <cstdint>

// ============================================================================
// Problem shapes (fixed by reference setup_inputs)
// ============================================================================
#define BATCH      4
#define NPTS       8192        // points per cloud
#define L_DIFF     98304       // 4*8192*3
#define L_STYLE    2048        // 4*512
#define L_CONTENT  1048576     // 4*1024*256
#define L_ID       98304

// chamfer tiling
#define THREADS    256
#define XT         4                       // rows per thread
#define XBLOCK     (THREADS * XT)          // 1024 rows per block
#define XCHUNKS    (NPTS / XBLOCK)         // 8
#define YSPLIT     4
#define YCHUNK     (NPTS / YSPLIT)         // 2048
#define TY         512                     // y tile in shared

// ============================================================================
// Scratch (device globals: no allocation allowed)
// ============================================================================
__device__ unsigned int g_min[2 * BATCH * NPTS];  // [dir][b][i] : bits of clamped min d2 (>=0)
__device__ double       g_acc[4];                  // diff, style, content, identity sums

// ============================================================================
// Packed f32x2 helpers (Blackwell; only reachable via PTX)
// ============================================================================
static __device__ __forceinline__ unsigned long long pk2(float lo, float hi) {
    unsigned long long r;
    asm("mov.b64 %0, {%1, %2};" : "=l"(r) : "f"(lo), "f"(hi));
    return r;
}
static __device__ __forceinline__ void upk2(unsigned long long v, float& lo, float& hi) {
    asm("mov.b64 {%0, %1}, %2;" : "=f"(lo), "=f"(hi) : "l"(v));
}
static __device__ __forceinline__ unsigned long long fma2(unsigned long long a,
                                                          unsigned long long b,
                                                          unsigned long long c) {
    unsigned long long d;
    asm("fma.rn.f32x2 %0, %1, %2, %3;" : "=l"(d) : "l"(a), "l"(b), "l"(c));
    return d;
}
static __device__ __forceinline__ unsigned long long mul2(unsigned long long a,
                                                          unsigned long long b) {
    unsigned long long d;
    asm("mul.rn.f32x2 %0, %1, %2;" : "=l"(d) : "l"(a), "l"(b));
    return d;
}

// ============================================================================
// Init: reset accumulators + min buffers (runs every replay -> deterministic)
// ============================================================================
__global__ void init_kernel() {
    int i = blockIdx.x * blockDim.x + threadIdx.x;
    if (i < 2 * BATCH * NPTS) g_min[i] = 0x7F800000u;  // +inf bits
    if (i < 4) g_acc[i] = 0.0;
}

// ============================================================================
// Chamfer min kernel.
// grid = (XCHUNKS, YSPLIT, 8)   z = dir*4 + b
//   dir 0: rows = x_original, cols = x_cycle   (cd1 mins)
//   dir 1: rows = x_cycle,    cols = x_original (cd2 mins)
// Each thread owns XT rows (x duplicated into packed regs), loops y in pairs.
// Inner: per 2 pairs = 4 packed-FMA (fma pipe) + 2 FMNMX (alu) + LDS.64 amortized.
// ============================================================================
__global__ void __launch_bounds__(THREADS)
chamfer_kernel(const float* __restrict__ xo, const float* __restrict__ xc) {
    const int z   = blockIdx.z;
    const int dir = z >> 2;
    const int b   = z & 3;
    const float* X = dir ? xc : xo;   // row points
    const float* Y = dir ? xo : xc;   // col points
    X += (size_t)b * NPTS * 3;
    Y += (size_t)b * NPTS * 3;
    unsigned int* outmin = g_min + ((size_t)dir * BATCH + b) * NPTS;

    __shared__ __align__(16) float sx[TY];
    __shared__ __align__(16) float sy[TY];
    __shared__ __align__(16) float sz[TY];
    __shared__ __align__(16) float st[TY];   // y^2

    const int t    = threadIdx.x;
    const int row0 = blockIdx.x * XBLOCK + t;

    unsigned long long rx[XT], ry[XT], rz[XT];
    float rsq[XT], rmin[XT];
#pragma unroll
    for (int r = 0; r < XT; r++) {
        int i = row0 + r * THREADS;
        float a = X[3 * i], bb = X[3 * i + 1], c = X[3 * i + 2];
        rx[r] = pk2(a, a);
        ry[r] = pk2(bb, bb);
        rz[r] = pk2(c, c);
        rsq[r]  = a * a + bb * bb + c * c;
        rmin[r] = 3.4e38f;
    }
    const unsigned long long neg2 = pk2(-2.0f, -2.0f);
    const int ybase = blockIdx.y * YCHUNK;

    for (int tile = 0; tile < YCHUNK; tile += TY) {
        for (int j = t; j < TY; j += THREADS) {
            int gj = ybase + tile + j;
            float a = Y[3 * gj], bb = Y[3 * gj + 1], c = Y[3 * gj + 2];
            sx[j] = a; sy[j] = bb; sz[j] = c;
            st[j] = a * a + bb * bb + c * c;
        }
        __syncthreads();

#pragma unroll 4
        for (int j = 0; j < TY; j += 2) {
            // packed pair of consecutive y points (broadcast across warp: conflict-free)
            unsigned long long yx = *(const unsigned long long*)(sx + j);
            unsigned long long yy = *(const unsigned long long*)(sy + j);
            unsigned long long yz = *(const unsigned long long*)(sz + j);
            unsigned long long yt = *(const unsigned long long*)(st + j);
#pragma unroll
            for (int r = 0; r < XT; r++) {
                unsigned long long d = mul2(rz[r], yz);
                d = fma2(ry[r], yy, d);
                d = fma2(rx[r], yx, d);
                unsigned long long term = fma2(d, neg2, yt);  // y^2 - 2*dot
                float lo, hi;
                upk2(term, lo, hi);
                rmin[r] = fminf(rmin[r], lo);
                rmin[r] = fminf(rmin[r], hi);
            }
        }
        __syncthreads();
    }

#pragma unroll
    for (int r = 0; r < XT; r++) {
        int i = row0 + r * THREADS;
        float d2 = fmaxf(rsq[r] + rmin[r], 0.0f);    // clamp like reference; >=0 -> uint order
        atomicMin(outmin + i, __float_as_uint(d2));
    }
}

// ============================================================================
// Fused MSE sums (4 pairs), double global accumulation.
// ============================================================================
__global__ void mse_kernel(const float* __restrict__ a0, const float* __restrict__ b0, int n0,
                           const float* __restrict__ a1, const float* __restrict__ b1, int n1,
                           const float* __restrict__ a2, const float* __restrict__ b2, int n2,
                           const float* __restrict__ a3, const float* __restrict__ b3, int n3) {
    const int gid    = blockIdx.x * blockDim.x + threadIdx.x;
    const int stride = gridDim.x * blockDim.x;
    float s[4] = {0.f, 0.f, 0.f, 0.f};
    for (int i = gid; i < n0; i += stride) { float d = a0[i] - b0[i]; s[0] += d * d; }
    for (int i = gid; i < n1; i += stride) { float d = a1[i] - b1[i]; s[1] += d * d; }
    for (int i = gid; i < n2; i += stride) { float d = a2[i] - b2[i]; s[2] += d * d; }
    for (int i = gid; i < n3; i += stride) { float d = a3[i] - b3[i]; s[3] += d * d; }

    __shared__ float smem[4];
    if (threadIdx.x < 4) smem[threadIdx.x] = 0.f;
    __syncthreads();
#pragma unroll
    for (int k = 0; k < 4; k++) {
#pragma unroll
        for (int off = 16; off > 0; off >>= 1)
            s[k] += __shfl_down_sync(0xFFFFFFFFu, s[k], off);
        if ((threadIdx.x & 31) == 0) atomicAdd(&smem[k], s[k]);
    }
    __syncthreads();
    if (threadIdx.x < 4) atomicAdd(&g_acc[threadIdx.x], (double)smem[threadIdx.x]);
}

// ============================================================================
// Final: sum sqrt(min d2) over all 65536 entries, combine everything.
// cycle = (sum of all sqrts) / (B * N * 2)
// ============================================================================
__global__ void final_kernel(float* __restrict__ out, int out_size) {
    __shared__ double s_cham;
    if (threadIdx.x == 0) s_cham = 0.0;
    __syncthreads();

    float local = 0.f;
    const int total = 2 * BATCH * NPTS;
    for (int i = threadIdx.x; i < total; i += blockDim.x)
        local += sqrtf(__uint_as_float(g_min[i]));
#pragma unroll
    for (int off = 16; off > 0; off >>= 1)
        local += __shfl_down_sync(0xFFFFFFFFu, local, off);
    if ((threadIdx.x & 31) == 0) atomicAdd(&s_cham, (double)local);
    __syncthreads();

    if (threadIdx.x == 0) {
        double diff     = g_acc[0] / (double)L_DIFF;
        double stylemse = g_acc[1] / (double)L_STYLE;
        double content  = g_acc[2] / (double)L_CONTENT;
        double identity = g_acc[3] / (double)L_ID;
        double cycle    = s_cham / (double)(BATCH * NPTS * 2);
        double style    = -stylemse;
        double tot = 1.0 * diff + 0.5 * style + 0.5 * content + 1.0 * cycle + 0.5 * identity;
        if (out_size > 0) out[0] = (float)diff;
        if (out_size > 1) out[1] = (float)style;
        if (out_size > 2) out[2] = (float)content;
        if (out_size > 3) out[3] = (float)cycle;
        if (out_size > 4) out[4] = (float)identity;
        if (out_size > 5) out[5] = (float)tot;
    }
    // zero any extra output slots (poisoned by harness)
    for (int i = 6 + (int)threadIdx.x; i < out_size; i += blockDim.x) out[i] = 0.f;
}

// ============================================================================
// Launch (graph-capturable: kernels only, no sync, no alloc)
// Inputs: 0 pred_noise, 1 target_noise, 2 style_sim, 3 style_real,
//         4 content_original, 5 content_generated, 6 x_cycle, 7 x_original,
//         8 x_identity
// ============================================================================
extern "C" void kernel_launch(void* const* d_in, const int* in_sizes, int n_in,
                              void* d_out, int out_size) {
    (void)n_in;
    const float* pred  = (const float*)d_in[0];
    const float* targ  = (const float*)d_in[1];
    const float* ssim  = (const float*)d_in[2];
    const float* sreal = (const float*)d_in[3];
    const float* corg  = (const float*)d_in[4];
    const float* cgen  = (const float*)d_in[5];
    const float* xcyc  = (const float*)d_in[6];
    const float* xorg  = (const float*)d_in[7];
    const float* xid   = (const float*)d_in[8];
    float* out = (float*)d_out;

    init_kernel<<<(2 * BATCH * NPTS + 1023) / 1024, 1024>>>();

    dim3 cgrid(XCHUNKS, YSPLIT, 2 * BATCH);
    chamfer_kernel<<<cgrid, THREADS>>>(xorg, xcyc);

    mse_kernel<<<128, 256>>>(pred, targ, in_sizes[0],
                             ssim, sreal, in_sizes[2],
                             corg, cgen, in_sizes[4],
                             xorg, xid, in_sizes[7]);

    final_kernel<<<1, 1024>>>(out, out_size);
}

// round 3
// speedup vs baseline: 1.2763x; 1.2763x over previous
#include <cuda_runtime.h>
#include <cstdint>

// ============================================================================
// Problem shapes (fixed by reference setup_inputs)
// ============================================================================
#define BATCH      4
#define NPTS       8192
#define L_DIFF     98304       // 4*8192*3
#define L_STYLE    2048        // 4*512
#define L_CONTENT  1048576     // 4*1024*256
#define L_ID       98304

// chamfer tiling: grid = (XCHUNKS, YSPLIT, 2*BATCH) = (16, 8, 8) = 1024 blocks
#define THREADS    128
#define XT         4                       // rows per thread
#define XBLOCK     (THREADS * XT)          // 512 rows per block
#define XCHUNKS    (NPTS / XBLOCK)         // 16
#define YSPLIT     8
#define YCHUNK     (NPTS / YSPLIT)         // 1024
#define TY         YCHUNK                  // single shared tile per block

// tail kernel
#define TAIL_BLOCKS   128
#define TAIL_THREADS  256

// ============================================================================
// Scratch (device globals: no allocation allowed).
// State protocol: every buffer is left "clean" (+inf / 0) by the TAIL kernel
// of each replay, so the next replay needs no init launch. Static initializers
// provide the clean state for the very first call.
// ============================================================================
__device__ unsigned int g_min[2 * BATCH * NPTS] = {};   // overwritten below
__device__ double       g_acc[4];                        // diff, style, content, identity
__device__ double       g_cham;                          // sum of sqrt(min d2)
__device__ unsigned int g_ctr;                           // last-block ticket

// g_min must start at +inf bits; a tiny one-time trick: chamfer uses atomicMin
// against it, so we set it from a constructor-free path: we instead reset it in
// the tail kernel AND seed it here via a separate __device__ initializer array.
// CUDA zero-inits by default; 0 bits = 0.0f which would break the FIRST run's
// atomicMin. So the launch path includes a one-shot-free init: the tail kernel
// always rewrites +inf, and for the first run we launch a cheap seed kernel —
// but that would be nondeterministic across calls. Instead: make chamfer's
// epilogue not need pre-init (see below: block-local full min when YSPLIT
// partials combine via atomicMin on a buffer that tail resets; for call #1 we
// still need +inf). Solution: initialize statically to +inf via explicit list
// is impractical (65536 entries) -> use a seed kernel EVERY call; it is only
// 65536 threads (~2us) and keeps determinism.
__global__ void seed_kernel() {
    int i = blockIdx.x * blockDim.x + threadIdx.x;
    if (i < 2 * BATCH * NPTS) g_min[i] = 0x7F800000u;   // +inf
    if (i == 0) { g_ctr = 0u; }
    if (i < 4)  { g_acc[i] = 0.0; }
    if (i == 4) { g_cham = 0.0; }
}

// ============================================================================
// Packed f32x2 helpers (Blackwell; only reachable via PTX)
// ============================================================================
static __device__ __forceinline__ unsigned long long pk2(float lo, float hi) {
    unsigned long long r;
    asm("mov.b64 %0, {%1, %2};" : "=l"(r) : "f"(lo), "f"(hi));
    return r;
}
static __device__ __forceinline__ void upk2(unsigned long long v, float& lo, float& hi) {
    asm("mov.b64 {%0, %1}, %2;" : "=f"(lo), "=f"(hi) : "l"(v));
}
static __device__ __forceinline__ unsigned long long fma2(unsigned long long a,
                                                          unsigned long long b,
                                                          unsigned long long c) {
    unsigned long long d;
    asm("fma.rn.f32x2 %0, %1, %2, %3;" : "=l"(d) : "l"(a), "l"(b), "l"(c));
    return d;
}
static __device__ __forceinline__ unsigned long long mul2(unsigned long long a,
                                                          unsigned long long b) {
    unsigned long long d;
    asm("mul.rn.f32x2 %0, %1, %2;" : "=l"(d) : "l"(a), "l"(b));
    return d;
}

// ============================================================================
// Chamfer min kernel.  grid = (XCHUNKS, YSPLIT, 8), z = dir*4 + b
//   dir 0: rows = x_original, cols = x_cycle   (cd1 mins)
//   dir 1: rows = x_cycle,    cols = x_original (cd2 mins)
// Inner loop per y-pair (XT=4): 16 packed FMA (fma pipe, binding: 32 cyc/SMSP)
// + 8 FMNMX (alu, absorbed) + 4 LDS.64 broadcast (absorbed).
// ============================================================================
__global__ void __launch_bounds__(THREADS)
chamfer_kernel(const float* __restrict__ xo, const float* __restrict__ xc) {
    const int z   = blockIdx.z;
    const int dir = z >> 2;
    const int b   = z & 3;
    const float* X = dir ? xc : xo;   // row points
    const float* Y = dir ? xo : xc;   // col points
    X += (size_t)b * NPTS * 3;
    Y += (size_t)b * NPTS * 3;
    unsigned int* outmin = g_min + ((size_t)dir * BATCH + b) * NPTS;

    __shared__ __align__(16) float sx[TY];
    __shared__ __align__(16) float sy[TY];
    __shared__ __align__(16) float sz[TY];
    __shared__ __align__(16) float st[TY];   // y^2

    const int t    = threadIdx.x;
    const int row0 = blockIdx.x * XBLOCK + t;

    unsigned long long rx[XT], ry[XT], rz[XT];
    float rsq[XT], rminL[XT], rminH[XT];
#pragma unroll
    for (int r = 0; r < XT; r++) {
        int i = row0 + r * THREADS;
        float a = X[3 * i], bb = X[3 * i + 1], c = X[3 * i + 2];
        rx[r] = pk2(a, a);
        ry[r] = pk2(bb, bb);
        rz[r] = pk2(c, c);
        rsq[r]   = a * a + bb * bb + c * c;
        rminL[r] = 3.4e38f;
        rminH[r] = 3.4e38f;
    }
    const unsigned long long neg2 = pk2(-2.0f, -2.0f);
    const int ybase = blockIdx.y * YCHUNK;

    // load the single y tile (1024 points)
    for (int j = t; j < TY; j += THREADS) {
        int gj = ybase + j;
        float a = Y[3 * gj], bb = Y[3 * gj + 1], c = Y[3 * gj + 2];
        sx[j] = a; sy[j] = bb; sz[j] = c;
        st[j] = a * a + bb * bb + c * c;
    }
    __syncthreads();

#pragma unroll 4
    for (int j = 0; j < TY; j += 2) {
        // packed pair of consecutive y points (warp-broadcast: conflict-free)
        unsigned long long yx = *(const unsigned long long*)(sx + j);
        unsigned long long yy = *(const unsigned long long*)(sy + j);
        unsigned long long yz = *(const unsigned long long*)(sz + j);
        unsigned long long yt = *(const unsigned long long*)(st + j);
#pragma unroll
        for (int r = 0; r < XT; r++) {
            unsigned long long d = mul2(rz[r], yz);
            d = fma2(ry[r], yy, d);
            d = fma2(rx[r], yx, d);
            unsigned long long term = fma2(d, neg2, yt);  // y^2 - 2*dot
            float lo, hi;
            upk2(term, lo, hi);
            rminL[r] = fminf(rminL[r], lo);   // two independent chains
            rminH[r] = fminf(rminH[r], hi);
        }
    }

#pragma unroll
    for (int r = 0; r < XT; r++) {
        int i = row0 + r * THREADS;
        float m  = fminf(rminL[r], rminH[r]);
        float d2 = fmaxf(rsq[r] + m, 0.0f);   // clamp like reference; >=0 -> uint order
        atomicMin(outmin + i, __float_as_uint(d2));
    }
}

// ============================================================================
// Fused tail kernel: all 4 MSE sums (vectorized float4) + chamfer sqrt-sum,
// last block combines and writes the 6 outputs. grid = TAIL_BLOCKS.
// ============================================================================
static __device__ __forceinline__ float mse_part_v4(const float4* __restrict__ a,
                                                    const float4* __restrict__ b,
                                                    int n4, int gid, int stride) {
    float s = 0.f;
    for (int i = gid; i < n4; i += stride) {
        float4 va = a[i], vb = b[i];
        float d0 = va.x - vb.x, d1 = va.y - vb.y, d2 = va.z - vb.z, d3 = va.w - vb.w;
        s += d0 * d0 + d1 * d1 + d2 * d2 + d3 * d3;
    }
    return s;
}

__global__ void __launch_bounds__(TAIL_THREADS)
tail_kernel(const float* __restrict__ pred,  const float* __restrict__ targ,
            const float* __restrict__ ssim,  const float* __restrict__ sreal,
            const float* __restrict__ corg,  const float* __restrict__ cgen,
            const float* __restrict__ xorg,  const float* __restrict__ xid,
            float* __restrict__ out, int out_size) {
    const int gid    = blockIdx.x * blockDim.x + threadIdx.x;
    const int stride = gridDim.x * blockDim.x;

    float s[4];
    s[0] = mse_part_v4((const float4*)pred, (const float4*)targ,  L_DIFF / 4,    gid, stride);
    s[1] = mse_part_v4((const float4*)ssim, (const float4*)sreal, L_STYLE / 4,   gid, stride);
    s[2] = mse_part_v4((const float4*)corg, (const float4*)cgen,  L_CONTENT / 4, gid, stride);
    s[3] = mse_part_v4((const float4*)xorg, (const float4*)xid,   L_ID / 4,      gid, stride);

    // chamfer sqrt-sum (g_min complete: previous kernel in stream) + reset to +inf
    float cham = 0.f;
    const int total = 2 * BATCH * NPTS;
    for (int i = gid; i < total; i += stride) {
        cham += sqrtf(__uint_as_float(g_min[i]));
        g_min[i] = 0x7F800000u;   // clean for next replay
    }

    __shared__ float  sm[5];
    __shared__ bool   s_last;
    if (threadIdx.x < 5) sm[threadIdx.x] = 0.f;
    __syncthreads();
#pragma unroll
    for (int k = 0; k < 4; k++) {
#pragma unroll
        for (int off = 16; off > 0; off >>= 1)
            s[k] += __shfl_down_sync(0xFFFFFFFFu, s[k], off);
        if ((threadIdx.x & 31) == 0) atomicAdd(&sm[k], s[k]);
    }
#pragma unroll
    for (int off = 16; off > 0; off >>= 1)
        cham += __shfl_down_sync(0xFFFFFFFFu, cham, off);
    if ((threadIdx.x & 31) == 0) atomicAdd(&sm[4], cham);
    __syncthreads();

    if (threadIdx.x < 4) atomicAdd(&g_acc[threadIdx.x], (double)sm[threadIdx.x]);
    if (threadIdx.x == 4) atomicAdd(&g_cham, (double)sm[4]);

    // last-block combine
    __threadfence();
    if (threadIdx.x == 0) {
        unsigned int ticket = atomicInc(&g_ctr, gridDim.x - 1);  // wraps to 0
        s_last = (ticket == gridDim.x - 1);
    }
    __syncthreads();
    if (s_last && threadIdx.x == 0) {
        double diff     = g_acc[0] / (double)L_DIFF;
        double stylemse = g_acc[1] / (double)L_STYLE;
        double content  = g_acc[2] / (double)L_CONTENT;
        double identity = g_acc[3] / (double)L_ID;
        double cycle    = g_cham / (double)(BATCH * NPTS * 2);
        double style    = -stylemse;
        double tot = diff + 0.5 * style + 0.5 * content + cycle + 0.5 * identity;
        if (out_size > 0) out[0] = (float)diff;
        if (out_size > 1) out[1] = (float)style;
        if (out_size > 2) out[2] = (float)content;
        if (out_size > 3) out[3] = (float)cycle;
        if (out_size > 4) out[4] = (float)identity;
        if (out_size > 5) out[5] = (float)tot;
        for (int i = 6; i < out_size; i++) out[i] = 0.f;
        // clean accumulators for next replay
        g_acc[0] = 0.0; g_acc[1] = 0.0; g_acc[2] = 0.0; g_acc[3] = 0.0;
        g_cham = 0.0;
    }
}

// ============================================================================
// Launch (graph-capturable). Inputs:
// 0 pred_noise, 1 target_noise, 2 style_sim, 3 style_real,
// 4 content_original, 5 content_generated, 6 x_cycle, 7 x_original, 8 x_identity
// ============================================================================
extern "C" void kernel_launch(void* const* d_in, const int* in_sizes, int n_in,
                              void* d_out, int out_size) {
    (void)n_in; (void)in_sizes;
    const float* pred  = (const float*)d_in[0];
    const float* targ  = (const float*)d_in[1];
    const float* ssim  = (const float*)d_in[2];
    const float* sreal = (const float*)d_in[3];
    const float* corg  = (const float*)d_in[4];
    const float* cgen  = (const float*)d_in[5];
    const float* xcyc  = (const float*)d_in[6];
    const float* xorg  = (const float*)d_in[7];
    const float* xid   = (const float*)d_in[8];
    float* out = (float*)d_out;

    seed_kernel<<<(2 * BATCH * NPTS + 1023) / 1024, 1024>>>();

    dim3 cgrid(XCHUNKS, YSPLIT, 2 * BATCH);
    chamfer_kernel<<<cgrid, THREADS>>>(xorg, xcyc);

    tail_kernel<<<TAIL_BLOCKS, TAIL_THREADS>>>(pred, targ, ssim, sreal,
                                               corg, cgen, xorg, xid,
                                               out, out_size);
}

// round 4
// speedup vs baseline: 1.3036x; 1.0214x over previous
#include <cuda_runtime.h>
#include <cstdint>

// ============================================================================
// Problem shapes (fixed by reference setup_inputs)
// ============================================================================
#define BATCH      4
#define NPTS       8192
#define L_DIFF     98304       // 4*8192*3
#define L_STYLE    2048        // 4*512
#define L_CONTENT  1048576     // 4*1024*256
#define L_ID       98304

// chamfer tiling: grid = (XCHUNKS, YSPLIT, 2*BATCH) = (16, 8, 8) = 1024 blocks
#define THREADS    128
#define XT         4                       // rows per thread
#define XBLOCK     (THREADS * XT)          // 512 rows per block
#define XCHUNKS    (NPTS / XBLOCK)         // 16
#define YSPLIT     8
#define YCHUNK     (NPTS / YSPLIT)         // 1024 y-points per block
#define NPAIR      (YCHUNK / 2)            // 512 packed y-pairs

// tail kernel
#define TAIL_BLOCKS   256
#define TAIL_THREADS  256

// ============================================================================
// Scratch (device globals; zero-initialized by CUDA).
// Encoding: g_enc[i] = 0xFFFFFFFF - float_bits(min d2). d2 >= 0 so every
// encoded value > 0 ==> the static/reset value 0 is the identity for
// atomicMax. Tail kernel resets everything to the clean (zero) state each
// call, so no init launch is needed and every call is deterministic.
// ============================================================================
__device__ unsigned int g_enc[2 * BATCH * NPTS];   // [dir][b][i]
__device__ double       g_acc[4];                   // diff, style, content, identity
__device__ double       g_cham;                     // sum of sqrt(min d2)
__device__ unsigned int g_ctr;                      // last-block ticket (auto-wrap)

// ============================================================================
// Packed f32x2 helpers (Blackwell; only reachable via PTX)
// ============================================================================
static __device__ __forceinline__ unsigned long long pk2(float lo, float hi) {
    unsigned long long r;
    asm("mov.b64 %0, {%1, %2};" : "=l"(r) : "f"(lo), "f"(hi));
    return r;
}
static __device__ __forceinline__ void upk2(unsigned long long v, float& lo, float& hi) {
    asm("mov.b64 {%0, %1}, %2;" : "=f"(lo), "=f"(hi) : "l"(v));
}
static __device__ __forceinline__ unsigned long long fma2(unsigned long long a,
                                                          unsigned long long b,
                                                          unsigned long long c) {
    unsigned long long d;
    asm("fma.rn.f32x2 %0, %1, %2, %3;" : "=l"(d) : "l"(a), "l"(b), "l"(c));
    return d;
}

// ============================================================================
// Chamfer min kernel.  grid = (XCHUNKS, YSPLIT, 8), z = dir*4 + b
//   dir 0: rows = x_original, cols = x_cycle   (cd1 mins)
//   dir 1: rows = x_cycle,    cols = x_original (cd2 mins)
// Row x premultiplied by -2:  term_j = y_j^2 + (-2x).y_j  (3 packed FMAs),
// full d2 = x^2 + min_j term_j, computed once in the epilogue.
// Inner per y-pair (XT=4 rows): 2 LDS.128 + 12 FFMA2 (fma pipe, binding)
// + 8 FMNMX (alu pipe).
// ============================================================================
__global__ void __launch_bounds__(THREADS)
chamfer_kernel(const float* __restrict__ xo, const float* __restrict__ xc) {
    const int z   = blockIdx.z;
    const int dir = z >> 2;
    const int b   = z & 3;
    const float* X = dir ? xc : xo;   // row points
    const float* Y = dir ? xo : xc;   // col points
    X += (size_t)b * NPTS * 3;
    Y += (size_t)b * NPTS * 3;
    unsigned int* outenc = g_enc + ((size_t)dir * BATCH + b) * NPTS;

    // interleaved packed y tile: s_ab[2p]={x2p.x, x2p+1.x}, s_ab[2p+1]={.y,.y}
    //                            s_cd[2p]={.z,.z},          s_cd[2p+1]={q,q}=y^2
    __shared__ __align__(16) unsigned long long s_ab[YCHUNK];
    __shared__ __align__(16) unsigned long long s_cd[YCHUNK];

    const int t    = threadIdx.x;
    const int row0 = blockIdx.x * XBLOCK + t;

    unsigned long long nx[XT], ny[XT], nz[XT];   // packed (-2*x) components
    float rsq[XT], rminL[XT], rminH[XT];
#pragma unroll
    for (int r = 0; r < XT; r++) {
        int i = row0 + r * THREADS;
        float a = X[3 * i], bb = X[3 * i + 1], c = X[3 * i + 2];
        nx[r] = pk2(-2.0f * a, -2.0f * a);
        ny[r] = pk2(-2.0f * bb, -2.0f * bb);
        nz[r] = pk2(-2.0f * c, -2.0f * c);
        rsq[r]   = a * a + bb * bb + c * c;
        rminL[r] = 3.4e38f;
        rminH[r] = 3.4e38f;
    }

    // fill y tile (pairs of consecutive points)
    const int ybase = blockIdx.y * YCHUNK;
    for (int p = t; p < NPAIR; p += THREADS) {
        const float* ya = Y + 3 * (ybase + 2 * p);
        float ax = ya[0], ay = ya[1], az = ya[2];
        float bx = ya[3], by = ya[4], bz = ya[5];
        float aq = ax * ax + ay * ay + az * az;
        float bq = bx * bx + by * by + bz * bz;
        s_ab[2 * p]     = pk2(ax, bx);
        s_ab[2 * p + 1] = pk2(ay, by);
        s_cd[2 * p]     = pk2(az, bz);
        s_cd[2 * p + 1] = pk2(aq, bq);
    }
    __syncthreads();

#pragma unroll 4
    for (int p = 0; p < NPAIR; p++) {
        // warp-broadcast 128-bit loads: conflict-free
        ulonglong2 v1 = *(const ulonglong2*)(s_ab + 2 * p);  // yx, yy
        ulonglong2 v2 = *(const ulonglong2*)(s_cd + 2 * p);  // yz, yq
#pragma unroll
        for (int r = 0; r < XT; r++) {
            unsigned long long term = fma2(nz[r], v2.x, v2.y);  // yq + nz*yz
            term = fma2(ny[r], v1.y, term);
            term = fma2(nx[r], v1.x, term);
            float lo, hi;
            upk2(term, lo, hi);
            rminL[r] = fminf(rminL[r], lo);   // two independent chains
            rminH[r] = fminf(rminH[r], hi);
        }
    }

#pragma unroll
    for (int r = 0; r < XT; r++) {
        int i = row0 + r * THREADS;
        float m  = fminf(rminL[r], rminH[r]);
        float d2 = fmaxf(rsq[r] + m, 0.0f);   // clamp like reference
        atomicMax(outenc + i, 0xFFFFFFFFu - __float_as_uint(d2));
    }
}

// ============================================================================
// Fused tail kernel: 4 MSE sums (float4) + chamfer sqrt-sum + state reset,
// last block combines and writes the 6 outputs. grid = TAIL_BLOCKS.
// ============================================================================
static __device__ __forceinline__ float mse_part_v4(const float4* __restrict__ a,
                                                    const float4* __restrict__ b,
                                                    int n4, int gid, int stride) {
    float s = 0.f;
    for (int i = gid; i < n4; i += stride) {
        float4 va = a[i], vb = b[i];
        float d0 = va.x - vb.x, d1 = va.y - vb.y, d2 = va.z - vb.z, d3 = va.w - vb.w;
        s += d0 * d0 + d1 * d1 + d2 * d2 + d3 * d3;
    }
    return s;
}

__global__ void __launch_bounds__(TAIL_THREADS)
tail_kernel(const float* __restrict__ pred,  const float* __restrict__ targ,
            const float* __restrict__ ssim,  const float* __restrict__ sreal,
            const float* __restrict__ corg,  const float* __restrict__ cgen,
            const float* __restrict__ xorg,  const float* __restrict__ xid,
            float* __restrict__ out, int out_size) {
    const int gid    = blockIdx.x * blockDim.x + threadIdx.x;
    const int stride = gridDim.x * blockDim.x;

    float s[4];
    s[0] = mse_part_v4((const float4*)pred, (const float4*)targ,  L_DIFF / 4,    gid, stride);
    s[1] = mse_part_v4((const float4*)ssim, (const float4*)sreal, L_STYLE / 4,   gid, stride);
    s[2] = mse_part_v4((const float4*)corg, (const float4*)cgen,  L_CONTENT / 4, gid, stride);
    s[3] = mse_part_v4((const float4*)xorg, (const float4*)xid,   L_ID / 4,      gid, stride);

    // chamfer sqrt-sum (g_enc complete: previous kernel in stream) + reset to 0
    float cham = 0.f;
    const int total = 2 * BATCH * NPTS;
    for (int i = gid; i < total; i += stride) {
        unsigned int bits = 0xFFFFFFFFu - g_enc[i];
        cham += sqrtf(__uint_as_float(bits));
        g_enc[i] = 0u;   // clean (atomicMax identity) for the next call
    }

    __shared__ float sm[5];
    __shared__ bool  s_last;
    if (threadIdx.x < 5) sm[threadIdx.x] = 0.f;
    __syncthreads();
#pragma unroll
    for (int k = 0; k < 4; k++) {
#pragma unroll
        for (int off = 16; off > 0; off >>= 1)
            s[k] += __shfl_down_sync(0xFFFFFFFFu, s[k], off);
        if ((threadIdx.x & 31) == 0) atomicAdd(&sm[k], s[k]);
    }
#pragma unroll
    for (int off = 16; off > 0; off >>= 1)
        cham += __shfl_down_sync(0xFFFFFFFFu, cham, off);
    if ((threadIdx.x & 31) == 0) atomicAdd(&sm[4], cham);
    __syncthreads();

    if (threadIdx.x < 4) atomicAdd(&g_acc[threadIdx.x], (double)sm[threadIdx.x]);
    if (threadIdx.x == 4) atomicAdd(&g_cham, (double)sm[4]);

    // last-block combine
    __threadfence();
    if (threadIdx.x == 0) {
        unsigned int ticket = atomicInc(&g_ctr, gridDim.x - 1);  // wraps to 0
        s_last = (ticket == gridDim.x - 1);
    }
    __syncthreads();
    if (s_last && threadIdx.x == 0) {
        double diff     = g_acc[0] / (double)L_DIFF;
        double stylemse = g_acc[1] / (double)L_STYLE;
        double content  = g_acc[2] / (double)L_CONTENT;
        double identity = g_acc[3] / (double)L_ID;
        double cycle    = g_cham / (double)(BATCH * NPTS * 2);
        double style    = -stylemse;
        double tot = diff + 0.5 * style + 0.5 * content + cycle + 0.5 * identity;
        if (out_size > 0) out[0] = (float)diff;
        if (out_size > 1) out[1] = (float)style;
        if (out_size > 2) out[2] = (float)content;
        if (out_size > 3) out[3] = (float)cycle;
        if (out_size > 4) out[4] = (float)identity;
        if (out_size > 5) out[5] = (float)tot;
        for (int i = 6; i < out_size; i++) out[i] = 0.f;
        // clean accumulators for the next call
        g_acc[0] = 0.0; g_acc[1] = 0.0; g_acc[2] = 0.0; g_acc[3] = 0.0;
        g_cham = 0.0;
    }
}

// ============================================================================
// Launch (graph-capturable). Inputs:
// 0 pred_noise, 1 target_noise, 2 style_sim, 3 style_real,
// 4 content_original, 5 content_generated, 6 x_cycle, 7 x_original, 8 x_identity
// ============================================================================
extern "C" void kernel_launch(void* const* d_in, const int* in_sizes, int n_in,
                              void* d_out, int out_size) {
    (void)n_in; (void)in_sizes;
    const float* pred  = (const float*)d_in[0];
    const float* targ  = (const float*)d_in[1];
    const float* ssim  = (const float*)d_in[2];
    const float* sreal = (const float*)d_in[3];
    const float* corg  = (const float*)d_in[4];
    const float* cgen  = (const float*)d_in[5];
    const float* xcyc  = (const float*)d_in[6];
    const float* xorg  = (const float*)d_in[7];
    const float* xid   = (const float*)d_in[8];
    float* out = (float*)d_out;

    dim3 cgrid(XCHUNKS, YSPLIT, 2 * BATCH);
    chamfer_kernel<<<cgrid, THREADS>>>(xorg, xcyc);

    tail_kernel<<<TAIL_BLOCKS, TAIL_THREADS>>>(pred, targ, ssim, sreal,
                                               corg, cgen, xorg, xid,
                                               out, out_size);
}

// round 5
// speedup vs baseline: 1.3325x; 1.0222x over previous
#include <cuda_runtime.h>
#include <cstdint>

// ============================================================================
// Problem shapes (fixed by reference setup_inputs)
// ============================================================================
#define BATCH      4
#define NPTS       8192
#define L_DIFF     98304       // 4*8192*3
#define L_STYLE    2048        // 4*512
#define L_CONTENT  1048576     // 4*1024*256
#define L_ID       98304

// fused kernel: 512 chamfer blocks + 80 mse blocks = 592 = 4 * 148 SMs
#define THREADS     128
#define XT          8                      // rows per thread
#define XBLOCK      (THREADS * XT)         // 1024 rows per block
#define XCHUNKS     (NPTS / XBLOCK)        // 8
#define YSPLIT      8
#define YCHUNK      (NPTS / YSPLIT)        // 1024 y-points per block
#define NPAIR       (YCHUNK / 2)           // 512 packed y-pairs
#define CH_BLOCKS   (XCHUNKS * YSPLIT * 2 * BATCH)   // 512
#define MSE_BLOCKS  80
#define ALL_BLOCKS  (CH_BLOCKS + MSE_BLOCKS)          // 592

// final kernel
#define FIN_BLOCKS  32
#define FIN_THREADS 256

// ============================================================================
// Scratch (device globals; zero-initialized by CUDA).
// g_enc[i] = 0xFFFFFFFF - float_bits(min d2); d2 >= 0 so every encoded value
// > 0 ==> 0 is the atomicMax identity == static init == post-reset state.
// final_kernel resets all state each call -> deterministic, no init launch.
// ============================================================================
__device__ unsigned int g_enc[2 * BATCH * NPTS];   // [dir][b][i]
__device__ double       g_acc[4];                   // diff, style, content, identity
__device__ double       g_cham;                     // sum of sqrt(min d2)
__device__ unsigned int g_ctr;                      // last-block ticket (auto-wrap)

// ============================================================================
// Packed f32x2 helpers (Blackwell; only reachable via PTX)
// ============================================================================
static __device__ __forceinline__ unsigned long long pk2(float lo, float hi) {
    unsigned long long r;
    asm("mov.b64 %0, {%1, %2};" : "=l"(r) : "f"(lo), "f"(hi));
    return r;
}
static __device__ __forceinline__ void upk2(unsigned long long v, float& lo, float& hi) {
    asm("mov.b64 {%0, %1}, %2;" : "=f"(lo), "=f"(hi) : "l"(v));
}
static __device__ __forceinline__ unsigned long long fma2(unsigned long long a,
                                                          unsigned long long b,
                                                          unsigned long long c) {
    unsigned long long d;
    asm("fma.rn.f32x2 %0, %1, %2, %3;" : "=l"(d) : "l"(a), "l"(b), "l"(c));
    return d;
}

// ============================================================================
// Chamfer tile (one block): 1024 x-rows vs 1024 y-points.
//   dir 0: rows = x_original, cols = x_cycle   (cd1 mins)
//   dir 1: rows = x_cycle,    cols = x_original (cd2 mins)
// Row x premultiplied by -2: term_j = y_j^2 + (-2x).y_j  (3 packed FMAs),
// d2 = x^2 + min_j term_j once in the epilogue.
// Per p-iter (y-pair, 16 values): 2 LDS.128 + 24 FFMA2 + 16 FMNMX.
// ============================================================================
static __device__ __forceinline__ void chamfer_tile(
    int bid, const float* __restrict__ xo, const float* __restrict__ xc,
    unsigned long long* s_ab, unsigned long long* s_cd) {

    const int xchunk = bid & (XCHUNKS - 1);
    const int ychunk = (bid >> 3) & (YSPLIT - 1);
    const int z      = bid >> 6;          // 0..7
    const int dir    = z >> 2;
    const int b      = z & 3;
    const float* X = dir ? xc : xo;
    const float* Y = dir ? xo : xc;
    X += (size_t)b * NPTS * 3;
    Y += (size_t)b * NPTS * 3;
    unsigned int* outenc = g_enc + ((size_t)dir * BATCH + b) * NPTS;

    const int t    = threadIdx.x;
    const int row0 = xchunk * XBLOCK + t;

    unsigned long long nx[XT], ny[XT], nz[XT];   // packed (-2*x) components
    float rsq[XT], rmin[XT];
#pragma unroll
    for (int r = 0; r < XT; r++) {
        int i = row0 + r * THREADS;
        float a = X[3 * i], bb = X[3 * i + 1], c = X[3 * i + 2];
        nx[r] = pk2(-2.0f * a, -2.0f * a);
        ny[r] = pk2(-2.0f * bb, -2.0f * bb);
        nz[r] = pk2(-2.0f * c, -2.0f * c);
        rsq[r]  = a * a + bb * bb + c * c;
        rmin[r] = 3.4e38f;
    }

    // fill y tile (pairs of consecutive points); interleaved for LDS.128:
    // s_ab[2p]={x,x'}, s_ab[2p+1]={y,y'}; s_cd[2p]={z,z'}, s_cd[2p+1]={q,q'}
    const int ybase = ychunk * YCHUNK;
    for (int p = t; p < NPAIR; p += THREADS) {
        const float* ya = Y + 3 * (ybase + 2 * p);
        float ax = ya[0], ay = ya[1], az = ya[2];
        float bx = ya[3], by = ya[4], bz = ya[5];
        s_ab[2 * p]     = pk2(ax, bx);
        s_ab[2 * p + 1] = pk2(ay, by);
        s_cd[2 * p]     = pk2(az, bz);
        s_cd[2 * p + 1] = pk2(ax * ax + ay * ay + az * az,
                              bx * bx + by * by + bz * bz);
    }
    __syncthreads();

#pragma unroll 2
    for (int p = 0; p < NPAIR; p++) {
        // warp-broadcast 128-bit loads: conflict-free
        ulonglong2 v1 = *(const ulonglong2*)(s_ab + 2 * p);  // yx, yy
        ulonglong2 v2 = *(const ulonglong2*)(s_cd + 2 * p);  // yz, yq
#pragma unroll
        for (int r = 0; r < XT; r++) {
            unsigned long long term = fma2(nz[r], v2.x, v2.y);  // yq + nz*yz
            term = fma2(ny[r], v1.y, term);
            term = fma2(nx[r], v1.x, term);
            float lo, hi;
            upk2(term, lo, hi);
            rmin[r] = fminf(rmin[r], fminf(lo, hi));
        }
    }

#pragma unroll
    for (int r = 0; r < XT; r++) {
        int i = row0 + r * THREADS;
        float d2 = fmaxf(rsq[r] + rmin[r], 0.0f);   // clamp like reference
        atomicMax(outenc + i, 0xFFFFFFFFu - __float_as_uint(d2));
    }
}

// ============================================================================
// MSE part (80 blocks): all 4 sums, float4-vectorized, overlapped with
// chamfer blocks inside the same launch. Results -> g_acc via atomicAdd.
// ============================================================================
static __device__ __forceinline__ float mse_part_v4(const float4* __restrict__ a,
                                                    const float4* __restrict__ b,
                                                    int n4, int gid, int stride) {
    float s = 0.f;
    for (int i = gid; i < n4; i += stride) {
        float4 va = a[i], vb = b[i];
        float d0 = va.x - vb.x, d1 = va.y - vb.y, d2 = va.z - vb.z, d3 = va.w - vb.w;
        s += d0 * d0 + d1 * d1 + d2 * d2 + d3 * d3;
    }
    return s;
}

static __device__ __forceinline__ void mse_blocks(
    int m, const float* pred, const float* targ, const float* ssim,
    const float* sreal, const float* corg, const float* cgen,
    const float* xorg, const float* xid) {

    const int gid    = m * THREADS + threadIdx.x;
    const int stride = MSE_BLOCKS * THREADS;

    float s[4];
    s[0] = mse_part_v4((const float4*)pred, (const float4*)targ,  L_DIFF / 4,    gid, stride);
    s[1] = mse_part_v4((const float4*)ssim, (const float4*)sreal, L_STYLE / 4,   gid, stride);
    s[2] = mse_part_v4((const float4*)corg, (const float4*)cgen,  L_CONTENT / 4, gid, stride);
    s[3] = mse_part_v4((const float4*)xorg, (const float4*)xid,   L_ID / 4,      gid, stride);

    __shared__ float sm[4];
    if (threadIdx.x < 4) sm[threadIdx.x] = 0.f;
    __syncthreads();
#pragma unroll
    for (int k = 0; k < 4; k++) {
#pragma unroll
        for (int off = 16; off > 0; off >>= 1)
            s[k] += __shfl_down_sync(0xFFFFFFFFu, s[k], off);
        if ((threadIdx.x & 31) == 0) atomicAdd(&sm[k], s[k]);
    }
    __syncthreads();
    if (threadIdx.x < 4) atomicAdd(&g_acc[threadIdx.x], (double)sm[threadIdx.x]);
}

// ============================================================================
// Fused kernel: blocks [0,512) chamfer tiles, blocks [512,592) MSE.
// ============================================================================
__global__ void __launch_bounds__(THREADS, 4)
fused_kernel(const float* __restrict__ xo,   const float* __restrict__ xc,
             const float* __restrict__ pred, const float* __restrict__ targ,
             const float* __restrict__ ssim, const float* __restrict__ sreal,
             const float* __restrict__ corg, const float* __restrict__ cgen,
             const float* __restrict__ xid) {
    __shared__ __align__(16) unsigned long long s_ab[YCHUNK];
    __shared__ __align__(16) unsigned long long s_cd[YCHUNK];

    const int bid = blockIdx.x;
    if (bid < CH_BLOCKS) {
        chamfer_tile(bid, xo, xc, s_ab, s_cd);
    } else {
        mse_blocks(bid - CH_BLOCKS, pred, targ, ssim, sreal, corg, cgen, xo, xid);
    }
}

// ============================================================================
// Final kernel: sqrt-sum of g_enc + reset, last block combines + writes out
// and cleans all state for the next call.
// ============================================================================
__global__ void __launch_bounds__(FIN_THREADS)
final_kernel(float* __restrict__ out, int out_size) {
    const int gid    = blockIdx.x * blockDim.x + threadIdx.x;
    const int stride = gridDim.x * blockDim.x;

    float cham = 0.f;
    const int total = 2 * BATCH * NPTS;
    for (int i = gid; i < total; i += stride) {
        unsigned int bits = 0xFFFFFFFFu - g_enc[i];
        cham += sqrtf(__uint_as_float(bits));
        g_enc[i] = 0u;   // clean (atomicMax identity) for next call
    }

    __shared__ float sm;
    __shared__ bool  s_last;
    if (threadIdx.x == 0) sm = 0.f;
    __syncthreads();
#pragma unroll
    for (int off = 16; off > 0; off >>= 1)
        cham += __shfl_down_sync(0xFFFFFFFFu, cham, off);
    if ((threadIdx.x & 31) == 0) atomicAdd(&sm, cham);
    __syncthreads();
    if (threadIdx.x == 0) atomicAdd(&g_cham, (double)sm);

    __threadfence();
    if (threadIdx.x == 0) {
        unsigned int ticket = atomicInc(&g_ctr, gridDim.x - 1);  // wraps to 0
        s_last = (ticket == gridDim.x - 1);
    }
    __syncthreads();
    if (s_last && threadIdx.x == 0) {
        double diff     = g_acc[0] / (double)L_DIFF;
        double stylemse = g_acc[1] / (double)L_STYLE;
        double content  = g_acc[2] / (double)L_CONTENT;
        double identity = g_acc[3] / (double)L_ID;
        double cycle    = g_cham / (double)(BATCH * NPTS * 2);
        double style    = -stylemse;
        double tot = diff + 0.5 * style + 0.5 * content + cycle + 0.5 * identity;
        if (out_size > 0) out[0] = (float)diff;
        if (out_size > 1) out[1] = (float)style;
        if (out_size > 2) out[2] = (float)content;
        if (out_size > 3) out[3] = (float)cycle;
        if (out_size > 4) out[4] = (float)identity;
        if (out_size > 5) out[5] = (float)tot;
        for (int i = 6; i < out_size; i++) out[i] = 0.f;
        g_acc[0] = 0.0; g_acc[1] = 0.0; g_acc[2] = 0.0; g_acc[3] = 0.0;
        g_cham = 0.0;
    }
}

// ============================================================================
// Launch (graph-capturable). Inputs:
// 0 pred_noise, 1 target_noise, 2 style_sim, 3 style_real,
// 4 content_original, 5 content_generated, 6 x_cycle, 7 x_original, 8 x_identity
// ============================================================================
extern "C" void kernel_launch(void* const* d_in, const int* in_sizes, int n_in,
                              void* d_out, int out_size) {
    (void)n_in; (void)in_sizes;
    const float* pred  = (const float*)d_in[0];
    const float* targ  = (const float*)d_in[1];
    const float* ssim  = (const float*)d_in[2];
    const float* sreal = (const float*)d_in[3];
    const float* corg  = (const float*)d_in[4];
    const float* cgen  = (const float*)d_in[5];
    const float* xcyc  = (const float*)d_in[6];
    const float* xorg  = (const float*)d_in[7];
    const float* xid   = (const float*)d_in[8];
    float* out = (float*)d_out;

    fused_kernel<<<ALL_BLOCKS, THREADS>>>(xorg, xcyc, pred, targ, ssim, sreal,
                                          corg, cgen, xid);

    final_kernel<<<FIN_BLOCKS, FIN_THREADS>>>(out, out_size);
}

// round 7
// speedup vs baseline: 1.3628x; 1.0227x over previous
#include <cuda_runtime.h>
#include <cstdint>

// ============================================================================
// Problem shapes (fixed by reference setup_inputs)
// ============================================================================
#define BATCH      4
#define NPTS       8192
#define L_DIFF     98304       // 4*8192*3
#define L_STYLE    2048        // 4*512
#define L_CONTENT  1048576     // 4*1024*256
#define L_ID       98304

// Symmetric chamfer tiling: each block does a 1024-row x 512-col tile of the
// distance matrix ONCE, producing both row-mins (cd1) and col-mins (cd2).
// grid = CH_I * CH_J * BATCH = 8*16*4 = 512 chamfer blocks + 80 MSE = 592
//      = exactly 4 blocks per SM (148 SMs) -> one balanced wave.
#define THREADS     128
#define XT          8                      // rows per thread
#define XBLOCK      (THREADS * XT)         // 1024 rows per block
#define CH_I        (NPTS / XBLOCK)        // 8
#define JT          512                    // cols per block
#define CH_J        (NPTS / JT)            // 16
#define NPAIR       (JT / 2)               // 256 packed col-pairs
#define CH_BLOCKS   (CH_I * CH_J * BATCH)  // 512
#define MSE_BLOCKS  80
#define ALL_BLOCKS  (CH_BLOCKS + MSE_BLOCKS)

// final kernel
#define FIN_BLOCKS  128
#define FIN_THREADS 256

// ============================================================================
// Scratch (device globals; zero-initialized by CUDA).
// g_enc[i] = 0xFFFFFFFF - float_bits(min d2); d2 >= 0 so every encoded value
// > 0 ==> 0 is the atomicMax identity == static init == post-reset state.
// final_kernel resets all state each call -> deterministic, no init launch.
// ============================================================================
__device__ unsigned int g_enc[2 * BATCH * NPTS];   // [dir][b][i]
__device__ double       g_acc[4];                   // diff, style, content, identity
__device__ double       g_cham;                     // sum of sqrt(min d2)
__device__ unsigned int g_ctr;                      // last-block ticket (auto-wrap)

// ============================================================================
// Packed f32x2 helpers (Blackwell; only reachable via PTX)
// ============================================================================
static __device__ __forceinline__ unsigned long long pk2(float lo, float hi) {
    unsigned long long r;
    asm("mov.b64 %0, {%1, %2};" : "=l"(r) : "f"(lo), "f"(hi));
    return r;
}
static __device__ __forceinline__ void upk2(unsigned long long v, float& lo, float& hi) {
    asm("mov.b64 {%0, %1}, %2;" : "=f"(lo), "=f"(hi) : "l"(v));
}
static __device__ __forceinline__ unsigned long long fma2(unsigned long long a,
                                                          unsigned long long b,
                                                          unsigned long long c) {
    unsigned long long d;
    asm("fma.rn.f32x2 %0, %1, %2, %3;" : "=l"(d) : "l"(a), "l"(b), "l"(c));
    return d;
}
static __device__ __forceinline__ unsigned long long mul2(unsigned long long a,
                                                          unsigned long long b) {
    unsigned long long d;
    asm("mul.rn.f32x2 %0, %1, %2;" : "=l"(d) : "l"(a), "l"(b));
    return d;
}
static __device__ __forceinline__ unsigned long long add2(unsigned long long a,
                                                          unsigned long long b) {
    unsigned long long d;
    asm("add.rn.f32x2 %0, %1, %2;" : "=l"(d) : "l"(a), "l"(b));
    return d;
}

// ============================================================================
// Symmetric chamfer tile.
// rows = x_original[b]  (row-min -> cd1 / g_enc dir0)
// cols = x_cycle[b]     (col-min -> cd2 / g_enc dir1)
// Per (row r, col-pair p): s = (-2x).y (mul2 + 2 fma2), then
//   t_row = s + q_j   (add2, 2-source)   -> row accumulator (registers)
//   t_col = s + rsq_i (add2, 2-source)   -> fold over r, butterfly over warp,
//                                           stage per-warp in shared.
// d2_row = rsq_i + min_j t_row ; d2_col = q_j + min_i t_col.
// ============================================================================
static __device__ __forceinline__ void chamfer_tile(
    int bid, const float* __restrict__ xo, const float* __restrict__ xc,
    unsigned long long* s_ab, unsigned long long* s_cd,
    unsigned long long* s_col) {

    const int b  = bid >> 7;           // batch
    const int ic = (bid >> 4) & 7;     // i-chunk
    const int jc = bid & 15;           // j-chunk
    const float* X = xo + (size_t)b * NPTS * 3;
    const float* Y = xc + (size_t)b * NPTS * 3;
    unsigned int* enc_row = g_enc + (size_t)b * NPTS;            // dir0
    unsigned int* enc_col = g_enc + (size_t)(BATCH + b) * NPTS;  // dir1

    const int t    = threadIdx.x;
    const int lane = t & 31;
    const int wid  = t >> 5;
    const int row0 = ic * XBLOCK + t;

    unsigned long long nx[XT], ny[XT], nz[XT], rsq2[XT];
    float rmin[XT];
#pragma unroll
    for (int r = 0; r < XT; r++) {
        int i = row0 + r * THREADS;
        float a = X[3 * i], bb = X[3 * i + 1], c = X[3 * i + 2];
        nx[r] = pk2(-2.0f * a, -2.0f * a);
        ny[r] = pk2(-2.0f * bb, -2.0f * bb);
        nz[r] = pk2(-2.0f * c, -2.0f * c);
        float q = a * a + bb * bb + c * c;
        rsq2[r] = pk2(q, q);
        rmin[r] = 3.4e38f;
    }

    // y tile (512 cols as 256 pairs), interleaved for LDS.128:
    // s_ab[2p]={x,x'}, s_ab[2p+1]={y,y'}; s_cd[2p]={z,z'}, s_cd[2p+1]={q,q'}
    const int jbase = jc * JT;
    for (int p = t; p < NPAIR; p += THREADS) {
        const float* ya = Y + 3 * (jbase + 2 * p);
        float ax = ya[0], ay = ya[1], az = ya[2];
        float bx = ya[3], by = ya[4], bz = ya[5];
        s_ab[2 * p]     = pk2(ax, bx);
        s_ab[2 * p + 1] = pk2(ay, by);
        s_cd[2 * p]     = pk2(az, bz);
        s_cd[2 * p + 1] = pk2(ax * ax + ay * ay + az * az,
                              bx * bx + by * by + bz * bz);
    }
    __syncthreads();

    for (int p = 0; p < NPAIR; p++) {
        // warp-broadcast 128-bit loads: conflict-free
        ulonglong2 v1 = *(const ulonglong2*)(s_ab + 2 * p);  // yx, yy
        ulonglong2 v2 = *(const ulonglong2*)(s_cd + 2 * p);  // yz, yq
        float cL = 3.4e38f, cH = 3.4e38f;
#pragma unroll
        for (int r = 0; r < XT; r++) {
            unsigned long long s = mul2(nx[r], v1.x);
            s = fma2(ny[r], v1.y, s);
            s = fma2(nz[r], v2.x, s);
            unsigned long long tr = add2(s, v2.y);     // + q_j  (2-source)
            unsigned long long tc = add2(s, rsq2[r]);  // + rsq_i (2-source)
            float rl, rh;  upk2(tr, rl, rh);
            rmin[r] = fminf(rmin[r], fminf(rl, rh));
            float c0, c1;  upk2(tc, c0, c1);
            cL = fminf(cL, c0);
            cH = fminf(cH, c1);
        }
        // warp butterfly: min over this warp's 256 rows for cols (2p, 2p+1)
#pragma unroll
        for (int off = 16; off > 0; off >>= 1) {
            cL = fminf(cL, __shfl_xor_sync(0xFFFFFFFFu, cL, off));
            cH = fminf(cH, __shfl_xor_sync(0xFFFFFFFFu, cH, off));
        }
        if (lane == 0) s_col[wid * NPAIR + p] = pk2(cL, cH);
    }

    // row epilogue
#pragma unroll
    for (int r = 0; r < XT; r++) {
        int i = row0 + r * THREADS;
        float q, dum;  upk2(rsq2[r], q, dum);
        float d2 = fmaxf(q + rmin[r], 0.0f);
        atomicMax(enc_row + i, 0xFFFFFFFFu - __float_as_uint(d2));
    }

    // col epilogue: merge 4 warps, add q_j, clamp, encode
    __syncthreads();
    for (int p = t; p < NPAIR; p += THREADS) {
        float aL, aH, bL, bH;
        upk2(s_col[0 * NPAIR + p], aL, aH);
        upk2(s_col[1 * NPAIR + p], bL, bH);
        aL = fminf(aL, bL);  aH = fminf(aH, bH);
        upk2(s_col[2 * NPAIR + p], bL, bH);
        aL = fminf(aL, bL);  aH = fminf(aH, bH);
        upk2(s_col[3 * NPAIR + p], bL, bH);
        aL = fminf(aL, bL);  aH = fminf(aH, bH);
        float q0, q1;  upk2(s_cd[2 * p + 1], q0, q1);
        float d2a = fmaxf(q0 + aL, 0.0f);
        float d2b = fmaxf(q1 + aH, 0.0f);
        int j = jbase + 2 * p;
        atomicMax(enc_col + j,     0xFFFFFFFFu - __float_as_uint(d2a));
        atomicMax(enc_col + j + 1, 0xFFFFFFFFu - __float_as_uint(d2b));
    }
}

// ============================================================================
// MSE part (80 blocks): all 4 sums, float4-vectorized, overlapped with
// chamfer blocks inside the same launch. Results -> g_acc via atomicAdd.
// ============================================================================
static __device__ __forceinline__ float mse_part_v4(const float4* __restrict__ a,
                                                    const float4* __restrict__ b,
                                                    int n4, int gid, int stride) {
    float s = 0.f;
    for (int i = gid; i < n4; i += stride) {
        float4 va = a[i], vb = b[i];
        float d0 = va.x - vb.x, d1 = va.y - vb.y, d2 = va.z - vb.z, d3 = va.w - vb.w;
        s += d0 * d0 + d1 * d1 + d2 * d2 + d3 * d3;
    }
    return s;
}

static __device__ __forceinline__ void mse_blocks(
    int m, const float* pred, const float* targ, const float* ssim,
    const float* sreal, const float* corg, const float* cgen,
    const float* xorg, const float* xid) {

    const int gid    = m * THREADS + threadIdx.x;
    const int stride = MSE_BLOCKS * THREADS;

    float s[4];
    s[0] = mse_part_v4((const float4*)pred, (const float4*)targ,  L_DIFF / 4,    gid, stride);
    s[1] = mse_part_v4((const float4*)ssim, (const float4*)sreal, L_STYLE / 4,   gid, stride);
    s[2] = mse_part_v4((const float4*)corg, (const float4*)cgen,  L_CONTENT / 4, gid, stride);
    s[3] = mse_part_v4((const float4*)xorg, (const float4*)xid,   L_ID / 4,      gid, stride);

    __shared__ float sm[4];
    if (threadIdx.x < 4) sm[threadIdx.x] = 0.f;
    __syncthreads();
#pragma unroll
    for (int k = 0; k < 4; k++) {
#pragma unroll
        for (int off = 16; off > 0; off >>= 1)
            s[k] += __shfl_down_sync(0xFFFFFFFFu, s[k], off);
        if ((threadIdx.x & 31) == 0) atomicAdd(&sm[k], s[k]);
    }
    __syncthreads();
    if (threadIdx.x < 4) atomicAdd(&g_acc[threadIdx.x], (double)sm[threadIdx.x]);
}

// ============================================================================
// Fused kernel: blocks [0,512) symmetric chamfer tiles, [512,592) MSE.
// ============================================================================
__global__ void __launch_bounds__(THREADS, 4)
fused_kernel(const float* __restrict__ xo,   const float* __restrict__ xc,
             const float* __restrict__ pred, const float* __restrict__ targ,
             const float* __restrict__ ssim, const float* __restrict__ sreal,
             const float* __restrict__ corg, const float* __restrict__ cgen,
             const float* __restrict__ xid) {
    __shared__ __align__(16) unsigned long long s_ab[JT];
    __shared__ __align__(16) unsigned long long s_cd[JT];
    __shared__ __align__(16) unsigned long long s_col[4 * NPAIR];

    const int bid = blockIdx.x;
    if (bid < CH_BLOCKS) {
        chamfer_tile(bid, xo, xc, s_ab, s_cd, s_col);
    } else {
        mse_blocks(bid - CH_BLOCKS, pred, targ, ssim, sreal, corg, cgen, xo, xid);
    }
}

// ============================================================================
// Final kernel: sqrt-sum of g_enc + reset, last block combines + writes out
// and cleans all state for the next call.
// ============================================================================
__global__ void __launch_bounds__(FIN_THREADS)
final_kernel(float* __restrict__ out, int out_size) {
    const int gid    = blockIdx.x * blockDim.x + threadIdx.x;
    const int stride = gridDim.x * blockDim.x;

    float cham = 0.f;
    const int total = 2 * BATCH * NPTS;
    for (int i = gid; i < total; i += stride) {
        unsigned int bits = 0xFFFFFFFFu - g_enc[i];
        cham += sqrtf(__uint_as_float(bits));
        g_enc[i] = 0u;   // clean (atomicMax identity) for next call
    }

    __shared__ float sm;
    __shared__ bool  s_last;
    if (threadIdx.x == 0) sm = 0.f;
    __syncthreads();
#pragma unroll
    for (int off = 16; off > 0; off >>= 1)
        cham += __shfl_down_sync(0xFFFFFFFFu, cham, off);
    if ((threadIdx.x & 31) == 0) atomicAdd(&sm, cham);
    __syncthreads();
    if (threadIdx.x == 0) atomicAdd(&g_cham, (double)sm);

    __threadfence();
    if (threadIdx.x == 0) {
        unsigned int ticket = atomicInc(&g_ctr, gridDim.x - 1);  // wraps to 0
        s_last = (ticket == gridDim.x - 1);
    }
    __syncthreads();
    if (s_last && threadIdx.x == 0) {
        double diff     = g_acc[0] / (double)L_DIFF;
        double stylemse = g_acc[1] / (double)L_STYLE;
        double content  = g_acc[2] / (double)L_CONTENT;
        double identity = g_acc[3] / (double)L_ID;
        double cycle    = g_cham / (double)(BATCH * NPTS * 2);
        double style    = -stylemse;
        double tot = diff + 0.5 * style + 0.5 * content + cycle + 0.5 * identity;
        if (out_size > 0) out[0] = (float)diff;
        if (out_size > 1) out[1] = (float)style;
        if (out_size > 2) out[2] = (float)content;
        if (out_size > 3) out[3] = (float)cycle;
        if (out_size > 4) out[4] = (float)identity;
        if (out_size > 5) out[5] = (float)tot;
        for (int i = 6; i < out_size; i++) out[i] = 0.f;
        g_acc[0] = 0.0; g_acc[1] = 0.0; g_acc[2] = 0.0; g_acc[3] = 0.0;
        g_cham = 0.0;
    }
}

// ============================================================================
// Launch (graph-capturable). Inputs:
// 0 pred_noise, 1 target_noise, 2 style_sim, 3 style_real,
// 4 content_original, 5 content_generated, 6 x_cycle, 7 x_original, 8 x_identity
// ============================================================================
extern "C" void kernel_launch(void* const* d_in, const int* in_sizes, int n_in,
                              void* d_out, int out_size) {
    (void)n_in; (void)in_sizes;
    const float* pred  = (const float*)d_in[0];
    const float* targ  = (const float*)d_in[1];
    const float* ssim  = (const float*)d_in[2];
    const float* sreal = (const float*)d_in[3];
    const float* corg  = (const float*)d_in[4];
    const float* cgen  = (const float*)d_in[5];
    const float* xcyc  = (const float*)d_in[6];
    const float* xorg  = (const float*)d_in[7];
    const float* xid   = (const float*)d_in[8];
    float* out = (float*)d_out;

    fused_kernel<<<ALL_BLOCKS, THREADS>>>(xorg, xcyc, pred, targ, ssim, sreal,
                                          corg, cgen, xid);

    final_kernel<<<FIN_BLOCKS, FIN_THREADS>>>(out, out_size);
}